// round 3
// baseline (speedup 1.0000x reference)
#include <cuda_runtime.h>

#define NS 25
#define NQ 200
#define FG 16
#define FL 64
#define FF 80      // FG + FL
#define D  512
#define WAY 5

#define KC 64      // K chunk
#define LDP 81     // padded smem stride (81 mod 32 = 17 -> conflict-free transposed stores)

// Scratch (allocation-free rule: __device__ globals)
__device__ float g_Sn[NS * FF * D];   // normalized, concatenated support  [2000, 512]
__device__ float g_Qn[NQ * FF * D];   // normalized, concatenated queries  [16000, 512]
__device__ float g_fro2[NS * NQ];     // squared-Frobenius distances

// ---------------------------------------------------------------------------
// Kernel 1: L2-normalize each 512-d feature vector, fusing the global/local
// concatenation. One warp per vector.
// ---------------------------------------------------------------------------
__global__ void norm_kernel(const float* __restrict__ sg,
                            const float* __restrict__ sl,
                            const float* __restrict__ qg,
                            const float* __restrict__ ql)
{
    int warp = (blockIdx.x * blockDim.x + threadIdx.x) >> 5;
    int lane = threadIdx.x & 31;
    const int total = (NS + NQ) * FF;
    if (warp >= total) return;

    const float* src;
    float* dst;
    if (warp < NS * FF) {
        int s = warp / FF, f = warp % FF;
        src = (f < FG) ? sg + (s * FG + f) * D
                       : sl + (s * FL + (f - FG)) * D;
        dst = g_Sn + warp * D;
    } else {
        int v = warp - NS * FF;
        int q = v / FF, f = v % FF;
        src = (f < FG) ? qg + (q * FG + f) * D
                       : ql + (q * FL + (f - FG)) * D;
        dst = g_Qn + v * D;
    }

    // 512 floats = 128 float4; 4 float4 per lane
    float4 v[4];
    float ss = 0.f;
#pragma unroll
    for (int i = 0; i < 4; i++) {
        v[i] = reinterpret_cast<const float4*>(src)[lane + 32 * i];
        ss += v[i].x * v[i].x + v[i].y * v[i].y + v[i].z * v[i].z + v[i].w * v[i].w;
    }
#pragma unroll
    for (int o = 16; o; o >>= 1)
        ss += __shfl_xor_sync(0xFFFFFFFFu, ss, o);

    float inv = 1.0f / fmaxf(sqrtf(ss), 1e-12f);
#pragma unroll
    for (int i = 0; i < 4; i++) {
        float4 w = v[i];
        w.x *= inv; w.y *= inv; w.z *= inv; w.w *= inv;
        reinterpret_cast<float4*>(dst)[lane + 32 * i] = w;
    }
}

// ---------------------------------------------------------------------------
// Kernel 2: fused cosine-GEMM + (1-sim)^2 Frobenius reduction.
// One CTA per (support s, query q) pair: C = Sn_s (80x512) * Qn_q^T (512x80),
// reduce sum((1-C)^2) -> g_fro2[s*NQ+q].
// 256 threads (16x16), each owns a 5x5 tile with stride-16 row/col mapping.
// FMA-pipe bound by design: 25 FMA : 10 LDS per k-step.
// ---------------------------------------------------------------------------
__global__ __launch_bounds__(256) void dist_kernel()
{
    __shared__ float As[KC * LDP];   // As[k][m], m = support feature row
    __shared__ float Bs[KC * LDP];   // Bs[k][n], n = query feature row
    __shared__ float red[256];

    const int s = blockIdx.y;
    const int q = blockIdx.x;
    const float* __restrict__ A = g_Sn + s * FF * D;
    const float* __restrict__ B = g_Qn + q * FF * D;

    const int tid = threadIdx.x;
    const int ty = tid >> 4;     // 0..15 -> rows ty + 16*i
    const int tx = tid & 15;     // 0..15 -> cols tx + 16*j

    float acc[5][5];
#pragma unroll
    for (int i = 0; i < 5; i++)
#pragma unroll
        for (int j = 0; j < 5; j++) acc[i][j] = 0.f;

    for (int k0 = 0; k0 < D; k0 += KC) {
        // Cooperative transposed load: 80 rows x 64 k-vals per matrix.
        // FF*(KC/4) = 1280 float4-slots, 5 per thread per matrix.
#pragma unroll
        for (int it = 0; it < 5; it++) {
            int idx = tid + it * 256;          // 0..1279
            int m  = idx >> 4;                 // row 0..79
            int kq = idx & 15;                 // float4 index within chunk
            float4 va = *reinterpret_cast<const float4*>(A + m * D + k0 + kq * 4);
            float4 vb = *reinterpret_cast<const float4*>(B + m * D + k0 + kq * 4);
            int base = (kq * 4) * LDP + m;
            As[base]           = va.x;
            As[base + LDP]     = va.y;
            As[base + 2 * LDP] = va.z;
            As[base + 3 * LDP] = va.w;
            Bs[base]           = vb.x;
            Bs[base + LDP]     = vb.y;
            Bs[base + 2 * LDP] = vb.z;
            Bs[base + 3 * LDP] = vb.w;
        }
        __syncthreads();

#pragma unroll 16
        for (int k = 0; k < KC; k++) {
            float a[5], b[5];
#pragma unroll
            for (int i = 0; i < 5; i++) a[i] = As[k * LDP + ty + 16 * i];
#pragma unroll
            for (int j = 0; j < 5; j++) b[j] = Bs[k * LDP + tx + 16 * j];
#pragma unroll
            for (int i = 0; i < 5; i++)
#pragma unroll
                for (int j = 0; j < 5; j++)
                    acc[i][j] += a[i] * b[j];
        }
        __syncthreads();
    }

    // Per-thread epilogue: sum (1 - sim)^2 over the 5x5 tile
    float p = 0.f;
#pragma unroll
    for (int i = 0; i < 5; i++)
#pragma unroll
        for (int j = 0; j < 5; j++) {
            float d = 1.0f - acc[i][j];
            p += d * d;
        }

    // Deterministic block tree-reduce
    red[tid] = p;
    __syncthreads();
#pragma unroll
    for (int st = 128; st > 0; st >>= 1) {
        if (tid < st) red[tid] += red[tid + st];
        __syncthreads();
    }
    if (tid == 0) g_fro2[s * NQ + q] = red[0];
}

// ---------------------------------------------------------------------------
// Kernel 3: class-mean + negate -> logits [nQ, WAY]
// cum = 2*fro2; logits[q][c] = -(1/count_c) * sum_{s: label==c} cum[s][q]
// ---------------------------------------------------------------------------
__global__ void logits_kernel(const long long* __restrict__ labels,
                              float* __restrict__ out)
{
    int t = blockIdx.x * blockDim.x + threadIdx.x;
    if (t >= NQ * WAY) return;
    int q = t / WAY;
    int c = t % WAY;
    float sum = 0.f;
    int cnt = 0;
#pragma unroll
    for (int s = 0; s < NS; s++) {
        if ((int)labels[s] == c) {
            sum += g_fro2[s * NQ + q];
            cnt++;
        }
    }
    out[t] = -(2.0f * sum) / (float)cnt;
}

// ---------------------------------------------------------------------------
extern "C" void kernel_launch(void* const* d_in, const int* in_sizes, int n_in,
                              void* d_out, int out_size)
{
    const float*     sg     = (const float*)d_in[0];   // [25,16,512]
    const float*     sl     = (const float*)d_in[1];   // [25,64,512]
    const long long* labels = (const long long*)d_in[2];
    const float*     qg     = (const float*)d_in[3];   // [200,16,512]
    const float*     ql     = (const float*)d_in[4];   // [200,64,512]
    float*           out    = (float*)d_out;           // [200,5]

    // Kernel 1: 18000 vectors, warp each, 8 warps/block
    int nvec = (NS + NQ) * FF;
    int blocks = (nvec * 32 + 255) / 256;
    norm_kernel<<<blocks, 256>>>(sg, sl, qg, ql);

    // Kernel 2: one CTA per (s,q)
    dist_kernel<<<dim3(NQ, NS), 256>>>();

    // Kernel 3: logits
    logits_kernel<<<(NQ * WAY + 255) / 256, 256>>>(labels, out);
}

// round 6
// speedup vs baseline: 4.9083x; 4.9083x over previous
#include <cuda_runtime.h>
#include <cuda_bf16.h>
#include <cstdint>

#define NS 25
#define NQ 200
#define FG 16
#define FL 64
#define FF 80
#define D  512
#define WAY 5

#define NSR (NS * FF)     // 2000 support rows (flat, no padding)
#define MT  128           // CTA M tile
#define NMT ((NSR + MT - 1) / MT)   // 16 M tiles
#define KC  64            // K chunk (bf16)
#define LDS_PAD 8
#define LDA (KC + LDS_PAD)  // 72 bf16 row stride -> conflict-free (36 banks)

// ---------------------------------------------------------------------------
// device scratch (allocation-free rule)
// ---------------------------------------------------------------------------
__device__ __nv_bfloat16 g_Sb[NSR * D];        // normalized support (bf16) [2000,512]
__device__ __nv_bfloat16 g_Qb[NQ * FF * D];    // normalized queries (bf16) [16000,512]
__device__ float g_fro2[NS * NQ];

// ---------------------------------------------------------------------------
// bf16 tensor-core mma (baseline PTX, valid on compute_103)
// ---------------------------------------------------------------------------
__device__ __forceinline__ void mma16816(float* c, const uint32_t* a,
                                         uint32_t b0, uint32_t b1) {
    asm volatile(
        "mma.sync.aligned.m16n8k16.row.col.f32.bf16.bf16.f32 "
        "{%0,%1,%2,%3}, {%4,%5,%6,%7}, {%8,%9}, {%0,%1,%2,%3};"
        : "+f"(c[0]), "+f"(c[1]), "+f"(c[2]), "+f"(c[3])
        : "r"(a[0]), "r"(a[1]), "r"(a[2]), "r"(a[3]), "r"(b0), "r"(b1));
}

// ---------------------------------------------------------------------------
// Kernel 1: L2-normalize + concat + bf16 convert. One warp per 512-d vector.
// ---------------------------------------------------------------------------
__global__ void norm_kernel(const float* __restrict__ sg, const float* __restrict__ sl,
                            const float* __restrict__ qg, const float* __restrict__ ql)
{
    int warp = (blockIdx.x * blockDim.x + threadIdx.x) >> 5;
    int lane = threadIdx.x & 31;
    const int total = NSR + NQ * FF;
    if (warp >= total) return;

    const float* src;
    __nv_bfloat162* dst;
    if (warp < NSR) {
        int s = warp / FF, f = warp % FF;
        src = (f < FG) ? sg + (s * FG + f) * D : sl + (s * FL + (f - FG)) * D;
        dst = reinterpret_cast<__nv_bfloat162*>(g_Sb + (size_t)warp * D);
    } else {
        int v = warp - NSR;
        int q = v / FF, f = v % FF;
        src = (f < FG) ? qg + (q * FG + f) * D : ql + (q * FL + (f - FG)) * D;
        dst = reinterpret_cast<__nv_bfloat162*>(g_Qb + (size_t)v * D);
    }

    float4 v[4];
    float ss = 0.f;
#pragma unroll
    for (int i = 0; i < 4; i++) {
        v[i] = reinterpret_cast<const float4*>(src)[lane + 32 * i];
        ss += v[i].x * v[i].x + v[i].y * v[i].y + v[i].z * v[i].z + v[i].w * v[i].w;
    }
#pragma unroll
    for (int o = 16; o; o >>= 1) ss += __shfl_xor_sync(0xFFFFFFFFu, ss, o);
    float inv = 1.0f / fmaxf(sqrtf(ss), 1e-12f);

#pragma unroll
    for (int i = 0; i < 4; i++) {
        __nv_bfloat162 h0 = __float22bfloat162_rn(make_float2(v[i].x * inv, v[i].y * inv));
        __nv_bfloat162 h1 = __float22bfloat162_rn(make_float2(v[i].z * inv, v[i].w * inv));
        dst[2 * (lane + 32 * i) + 0] = h0;
        dst[2 * (lane + 32 * i) + 1] = h1;
    }
}

// ---------------------------------------------------------------------------
// Kernel 1b: zero the fro2 accumulator
// ---------------------------------------------------------------------------
__global__ void zero_kernel()
{
    int t = blockIdx.x * blockDim.x + threadIdx.x;
    if (t < NS * NQ) g_fro2[t] = 0.f;
}

// ---------------------------------------------------------------------------
// Kernel 2: tensor-core fused distance kernel.
// CTA = (M tile tm of flat support rows, query q): C[128x80] = A_tile * B_q^T,
// epilogue: per-row sum of (1-c)^2, scattered to fro2[row/80][q] by atomicAdd.
// 8 warps in 4x2 grid; per warp 2 m16-tiles x 5 n8-tiles; K chunked by 64.
// ---------------------------------------------------------------------------
__global__ __launch_bounds__(256) void dist_kernel()
{
    __shared__ __align__(16) __nv_bfloat16 As[MT][LDA];
    __shared__ __align__(16) __nv_bfloat16 Bs[FF][LDA];
    __shared__ float red[MT];

    const int q  = blockIdx.x;
    const int tm = blockIdx.y;
    const int tid  = threadIdx.x;
    const int lane = tid & 31;
    const int wid  = tid >> 5;
    const int wy   = wid >> 1;          // 0..3 -> 32 M rows each
    const int wx   = wid & 1;           // 0..1 -> 40 N cols each
    const int qr   = lane >> 2;         // 0..7
    const int qc   = lane & 3;          // 0..3

    const __nv_bfloat16* __restrict__ Bg = g_Qb + (size_t)q * FF * D;

    float acc[2][5][4];
#pragma unroll
    for (int mt = 0; mt < 2; mt++)
#pragma unroll
        for (int nt = 0; nt < 5; nt++)
#pragma unroll
            for (int r = 0; r < 4; r++) acc[mt][nt][r] = 0.f;

    for (int k0 = 0; k0 < D; k0 += KC) {
        // --- load A chunk: 128 rows x 64 k (uint4 = 8 bf16), 4 per thread ---
#pragma unroll
        for (int i = 0; i < 4; i++) {
            int idx = tid + i * 256;          // 0..1023
            int row = idx >> 3, colv = idx & 7;
            int grow = tm * MT + row;
            if (grow > NSR - 1) grow = NSR - 1;   // clamp (masked in epilogue)
            uint4 v = *reinterpret_cast<const uint4*>(g_Sb + (size_t)grow * D + k0 + colv * 8);
            *reinterpret_cast<uint4*>(&As[row][colv * 8]) = v;
        }
        // --- load B chunk: 80 rows x 64 k -> 640 uint4 ---
#pragma unroll
        for (int i = 0; i < 3; i++) {
            int idx = tid + i * 256;
            if (idx < FF * 8) {
                int row = idx >> 3, colv = idx & 7;
                uint4 v = *reinterpret_cast<const uint4*>(Bg + (size_t)row * D + k0 + colv * 8);
                *reinterpret_cast<uint4*>(&Bs[row][colv * 8]) = v;
            }
        }
        __syncthreads();

#pragma unroll
        for (int ks = 0; ks < KC / 16; ks++) {
            const int k = ks * 16;
            uint32_t a[2][4];
#pragma unroll
            for (int mt = 0; mt < 2; mt++) {
                int r = wy * 32 + mt * 16 + qr;
                a[mt][0] = *reinterpret_cast<const uint32_t*>(&As[r][k + qc * 2]);
                a[mt][1] = *reinterpret_cast<const uint32_t*>(&As[r + 8][k + qc * 2]);
                a[mt][2] = *reinterpret_cast<const uint32_t*>(&As[r][k + qc * 2 + 8]);
                a[mt][3] = *reinterpret_cast<const uint32_t*>(&As[r + 8][k + qc * 2 + 8]);
            }
#pragma unroll
            for (int nt = 0; nt < 5; nt++) {
                int rn = wx * 40 + nt * 8 + qr;
                uint32_t b0 = *reinterpret_cast<const uint32_t*>(&Bs[rn][k + qc * 2]);
                uint32_t b1 = *reinterpret_cast<const uint32_t*>(&Bs[rn][k + qc * 2 + 8]);
                mma16816(acc[0][nt], a[0], b0, b1);
                mma16816(acc[1][nt], a[1], b0, b1);
            }
        }
        __syncthreads();
    }

    // --- epilogue: per-thread row partials of sum (1 - c)^2 ---
    if (tid < MT) red[tid] = 0.f;
    __syncthreads();

#pragma unroll
    for (int mt = 0; mt < 2; mt++) {
        float p0 = 0.f, p1 = 0.f;
#pragma unroll
        for (int nt = 0; nt < 5; nt++) {
            float d0 = 1.0f - acc[mt][nt][0];
            float d1 = 1.0f - acc[mt][nt][1];
            float d2 = 1.0f - acc[mt][nt][2];
            float d3 = 1.0f - acc[mt][nt][3];
            p0 += d0 * d0 + d1 * d1;   // row qr
            p1 += d2 * d2 + d3 * d3;   // row qr + 8
        }
        int r = wy * 32 + mt * 16 + qr;
        atomicAdd(&red[r], p0);
        atomicAdd(&red[r + 8], p1);
    }
    __syncthreads();

    if (tid < MT) {
        int grow = tm * MT + tid;
        if (grow < NSR)
            atomicAdd(&g_fro2[(grow / FF) * NQ + q], red[tid]);
    }
}

// ---------------------------------------------------------------------------
// Kernel 3: class-mean + negate -> logits [nQ, WAY]
// ---------------------------------------------------------------------------
__global__ void logits_kernel(const long long* __restrict__ labels,
                              float* __restrict__ out)
{
    int t = blockIdx.x * blockDim.x + threadIdx.x;
    if (t >= NQ * WAY) return;
    int q = t / WAY, c = t % WAY;
    float sum = 0.f; int cnt = 0;
#pragma unroll
    for (int s = 0; s < NS; s++) {
        if ((int)labels[s] == c) { sum += g_fro2[s * NQ + q]; cnt++; }
    }
    out[t] = -(2.0f * sum) / (float)cnt;
}

// ---------------------------------------------------------------------------
extern "C" void kernel_launch(void* const* d_in, const int* in_sizes, int n_in,
                              void* d_out, int out_size)
{
    const float*     sg     = (const float*)d_in[0];   // [25,16,512]
    const float*     sl     = (const float*)d_in[1];   // [25,64,512]
    const long long* labels = (const long long*)d_in[2];
    const float*     qg     = (const float*)d_in[3];   // [200,16,512]
    const float*     ql     = (const float*)d_in[4];   // [200,64,512]
    float*           out    = (float*)d_out;           // [200,5]

    int nvec = NSR + NQ * FF;  // 18000 vectors, one warp each
    norm_kernel<<<(nvec * 32 + 255) / 256, 256>>>(sg, sl, qg, ql);

    zero_kernel<<<(NS * NQ + 255) / 256, 256>>>();

    dist_kernel<<<dim3(NQ, NMT), 256>>>();

    logits_kernel<<<(NQ * WAY + 255) / 256, 256>>>(labels, out);
}

// round 9
// speedup vs baseline: 5.0133x; 1.0214x over previous
#include <cuda_runtime.h>
#include <cuda_bf16.h>
#include <cstdint>

#define NS 25
#define NQ 200
#define FG 16
#define FL 64
#define FF 80
#define D  512
#define WAY 5

#define NSR (NS * FF)     // 2000 support rows (flat, no padding)
#define MT  128           // CTA M tile
#define NMT ((NSR + MT - 1) / MT)   // 16 M tiles
#define KC  64            // K chunk (bf16)
#define LDS_PAD 8
#define LDA (KC + LDS_PAD)  // 72 bf16 row stride -> conflict-free (36 banks)

// ---------------------------------------------------------------------------
// device scratch (allocation-free rule)
// ---------------------------------------------------------------------------
__device__ __nv_bfloat16 g_Sb[NSR * D];        // normalized support (bf16) [2000,512]
__device__ __nv_bfloat16 g_Qb[NQ * FF * D];    // normalized queries (bf16) [16000,512]
__device__ float g_fro2[NS * NQ];

// ---------------------------------------------------------------------------
// bf16 tensor-core mma (baseline PTX, valid on compute_103)
// ---------------------------------------------------------------------------
__device__ __forceinline__ void mma16816(float* c, const uint32_t* a,
                                         uint32_t b0, uint32_t b1) {
    asm volatile(
        "mma.sync.aligned.m16n8k16.row.col.f32.bf16.bf16.f32 "
        "{%0,%1,%2,%3}, {%4,%5,%6,%7}, {%8,%9}, {%0,%1,%2,%3};"
        : "+f"(c[0]), "+f"(c[1]), "+f"(c[2]), "+f"(c[3])
        : "r"(a[0]), "r"(a[1]), "r"(a[2]), "r"(a[3]), "r"(b0), "r"(b1));
}

// ---------------------------------------------------------------------------
// Kernel 1: L2-normalize + concat + bf16 convert. One warp per 512-d vector.
// ---------------------------------------------------------------------------
__global__ void norm_kernel(const float* __restrict__ sg, const float* __restrict__ sl,
                            const float* __restrict__ qg, const float* __restrict__ ql)
{
    int warp = (blockIdx.x * blockDim.x + threadIdx.x) >> 5;
    int lane = threadIdx.x & 31;
    const int total = NSR + NQ * FF;
    if (warp >= total) return;

    const float* src;
    __nv_bfloat162* dst;
    if (warp < NSR) {
        int s = warp / FF, f = warp % FF;
        src = (f < FG) ? sg + (s * FG + f) * D : sl + (s * FL + (f - FG)) * D;
        dst = reinterpret_cast<__nv_bfloat162*>(g_Sb + (size_t)warp * D);
    } else {
        int v = warp - NSR;
        int q = v / FF, f = v % FF;
        src = (f < FG) ? qg + (q * FG + f) * D : ql + (q * FL + (f - FG)) * D;
        dst = reinterpret_cast<__nv_bfloat162*>(g_Qb + (size_t)v * D);
    }

    float4 v[4];
    float ss = 0.f;
#pragma unroll
    for (int i = 0; i < 4; i++) {
        v[i] = reinterpret_cast<const float4*>(src)[lane + 32 * i];
        ss += v[i].x * v[i].x + v[i].y * v[i].y + v[i].z * v[i].z + v[i].w * v[i].w;
    }
#pragma unroll
    for (int o = 16; o; o >>= 1) ss += __shfl_xor_sync(0xFFFFFFFFu, ss, o);
    float inv = 1.0f / fmaxf(sqrtf(ss), 1e-12f);

#pragma unroll
    for (int i = 0; i < 4; i++) {
        __nv_bfloat162 h0 = __float22bfloat162_rn(make_float2(v[i].x * inv, v[i].y * inv));
        __nv_bfloat162 h1 = __float22bfloat162_rn(make_float2(v[i].z * inv, v[i].w * inv));
        dst[2 * (lane + 32 * i) + 0] = h0;
        dst[2 * (lane + 32 * i) + 1] = h1;
    }
}

// ---------------------------------------------------------------------------
// Kernel 1b: zero the fro2 accumulator
// ---------------------------------------------------------------------------
__global__ void zero_kernel()
{
    int t = blockIdx.x * blockDim.x + threadIdx.x;
    if (t < NS * NQ) g_fro2[t] = 0.f;
}

// ---------------------------------------------------------------------------
// Kernel 2: tensor-core fused distance kernel.
// CTA = (M tile tm of flat support rows, query q): C[128x80] = A_tile * B_q^T,
// epilogue: per-row sum of (1-c)^2, scattered to fro2[row/80][q] by atomicAdd.
// 8 warps in 4x2 grid; per warp 2 m16-tiles x 5 n8-tiles; K chunked by 64.
// ---------------------------------------------------------------------------
__global__ __launch_bounds__(256) void dist_kernel()
{
    __shared__ __align__(16) __nv_bfloat16 As[MT][LDA];
    __shared__ __align__(16) __nv_bfloat16 Bs[FF][LDA];
    __shared__ float red[MT];

    const int q  = blockIdx.x;
    const int tm = blockIdx.y;
    const int tid  = threadIdx.x;
    const int lane = tid & 31;
    const int wid  = tid >> 5;
    const int wy   = wid >> 1;          // 0..3 -> 32 M rows each
    const int wx   = wid & 1;           // 0..1 -> 40 N cols each
    const int qr   = lane >> 2;         // 0..7
    const int qc   = lane & 3;          // 0..3

    const __nv_bfloat16* __restrict__ Bg = g_Qb + (size_t)q * FF * D;

    float acc[2][5][4];
#pragma unroll
    for (int mt = 0; mt < 2; mt++)
#pragma unroll
        for (int nt = 0; nt < 5; nt++)
#pragma unroll
            for (int r = 0; r < 4; r++) acc[mt][nt][r] = 0.f;

    for (int k0 = 0; k0 < D; k0 += KC) {
        // --- load A chunk: 128 rows x 64 k (uint4 = 8 bf16), 4 per thread ---
#pragma unroll
        for (int i = 0; i < 4; i++) {
            int idx = tid + i * 256;          // 0..1023
            int row = idx >> 3, colv = idx & 7;
            int grow = tm * MT + row;
            if (grow > NSR - 1) grow = NSR - 1;   // clamp (masked in epilogue)
            uint4 v = *reinterpret_cast<const uint4*>(g_Sb + (size_t)grow * D + k0 + colv * 8);
            *reinterpret_cast<uint4*>(&As[row][colv * 8]) = v;
        }
        // --- load B chunk: 80 rows x 64 k -> 640 uint4 ---
#pragma unroll
        for (int i = 0; i < 3; i++) {
            int idx = tid + i * 256;
            if (idx < FF * 8) {
                int row = idx >> 3, colv = idx & 7;
                uint4 v = *reinterpret_cast<const uint4*>(Bg + (size_t)row * D + k0 + colv * 8);
                *reinterpret_cast<uint4*>(&Bs[row][colv * 8]) = v;
            }
        }
        __syncthreads();

#pragma unroll
        for (int ks = 0; ks < KC / 16; ks++) {
            const int k = ks * 16;
            uint32_t a[2][4];
#pragma unroll
            for (int mt = 0; mt < 2; mt++) {
                int r = wy * 32 + mt * 16 + qr;
                a[mt][0] = *reinterpret_cast<const uint32_t*>(&As[r][k + qc * 2]);
                a[mt][1] = *reinterpret_cast<const uint32_t*>(&As[r + 8][k + qc * 2]);
                a[mt][2] = *reinterpret_cast<const uint32_t*>(&As[r][k + qc * 2 + 8]);
                a[mt][3] = *reinterpret_cast<const uint32_t*>(&As[r + 8][k + qc * 2 + 8]);
            }
#pragma unroll
            for (int nt = 0; nt < 5; nt++) {
                int rn = wx * 40 + nt * 8 + qr;
                uint32_t b0 = *reinterpret_cast<const uint32_t*>(&Bs[rn][k + qc * 2]);
                uint32_t b1 = *reinterpret_cast<const uint32_t*>(&Bs[rn][k + qc * 2 + 8]);
                mma16816(acc[0][nt], a[0], b0, b1);
                mma16816(acc[1][nt], a[1], b0, b1);
            }
        }
        __syncthreads();
    }

    // --- epilogue: per-thread row partials of sum (1 - c)^2 ---
    if (tid < MT) red[tid] = 0.f;
    __syncthreads();

#pragma unroll
    for (int mt = 0; mt < 2; mt++) {
        float p0 = 0.f, p1 = 0.f;
#pragma unroll
        for (int nt = 0; nt < 5; nt++) {
            float d0 = 1.0f - acc[mt][nt][0];
            float d1 = 1.0f - acc[mt][nt][1];
            float d2 = 1.0f - acc[mt][nt][2];
            float d3 = 1.0f - acc[mt][nt][3];
            p0 += d0 * d0 + d1 * d1;   // row qr
            p1 += d2 * d2 + d3 * d3;   // row qr + 8
        }
        int r = wy * 32 + mt * 16 + qr;
        atomicAdd(&red[r], p0);
        atomicAdd(&red[r + 8], p1);
    }
    __syncthreads();

    if (tid < MT) {
        int grow = tm * MT + tid;
        if (grow < NSR)
            atomicAdd(&g_fro2[(grow / FF) * NQ + q], red[tid]);
    }
}

// ---------------------------------------------------------------------------
// Kernel 3: class-mean + negate -> logits [nQ, WAY]
// ---------------------------------------------------------------------------
__global__ void logits_kernel(const long long* __restrict__ labels,
                              float* __restrict__ out)
{
    int t = blockIdx.x * blockDim.x + threadIdx.x;
    if (t >= NQ * WAY) return;
    int q = t / WAY, c = t % WAY;
    float sum = 0.f; int cnt = 0;
#pragma unroll
    for (int s = 0; s < NS; s++) {
        if ((int)labels[s] == c) { sum += g_fro2[s * NQ + q]; cnt++; }
    }
    out[t] = -(2.0f * sum) / (float)cnt;
}

// ---------------------------------------------------------------------------
extern "C" void kernel_launch(void* const* d_in, const int* in_sizes, int n_in,
                              void* d_out, int out_size)
{
    const float*     sg     = (const float*)d_in[0];   // [25,16,512]
    const float*     sl     = (const float*)d_in[1];   // [25,64,512]
    const long long* labels = (const long long*)d_in[2];
    const float*     qg     = (const float*)d_in[3];   // [200,16,512]
    const float*     ql     = (const float*)d_in[4];   // [200,64,512]
    float*           out    = (float*)d_out;           // [200,5]

    int nvec = NSR + NQ * FF;  // 18000 vectors, one warp each
    norm_kernel<<<(nvec * 32 + 255) / 256, 256>>>(sg, sl, qg, ql);

    zero_kernel<<<(NS * NQ + 255) / 256, 256>>>();

    dist_kernel<<<dim3(NQ, NMT), 256>>>();

    logits_kernel<<<(NQ * WAY + 255) / 256, 256>>>(labels, out);
}

// round 10
// speedup vs baseline: 5.0143x; 1.0002x over previous
#include <cuda_runtime.h>
#include <cuda_bf16.h>
#include <cstdint>

#define NS 25
#define NQ 200
#define FG 16
#define FL 64
#define FF 80
#define D  512
#define WAY 5

#define NSR (NS * FF)     // 2000 support rows (flat, no padding)
#define MT  128           // CTA M tile
#define NMT ((NSR + MT - 1) / MT)   // 16 M tiles
#define KC  64            // K chunk (bf16)
#define LDS_PAD 8
#define LDA (KC + LDS_PAD)  // 72 bf16 row stride -> conflict-free (36 banks)

// ---------------------------------------------------------------------------
// device scratch (allocation-free rule)
// ---------------------------------------------------------------------------
__device__ __nv_bfloat16 g_Sb[NSR * D];        // normalized support (bf16) [2000,512]
__device__ __nv_bfloat16 g_Qb[NQ * FF * D];    // normalized queries (bf16) [16000,512]
__device__ float g_fro2[NS * NQ];

// ---------------------------------------------------------------------------
// bf16 tensor-core mma (baseline PTX, valid on compute_103)
// ---------------------------------------------------------------------------
__device__ __forceinline__ void mma16816(float* c, const uint32_t* a,
                                         uint32_t b0, uint32_t b1) {
    asm volatile(
        "mma.sync.aligned.m16n8k16.row.col.f32.bf16.bf16.f32 "
        "{%0,%1,%2,%3}, {%4,%5,%6,%7}, {%8,%9}, {%0,%1,%2,%3};"
        : "+f"(c[0]), "+f"(c[1]), "+f"(c[2]), "+f"(c[3])
        : "r"(a[0]), "r"(a[1]), "r"(a[2]), "r"(a[3]), "r"(b0), "r"(b1));
}

// ---------------------------------------------------------------------------
// Kernel 1: L2-normalize + concat + bf16 convert. One warp per 512-d vector.
// ---------------------------------------------------------------------------
__global__ void norm_kernel(const float* __restrict__ sg, const float* __restrict__ sl,
                            const float* __restrict__ qg, const float* __restrict__ ql)
{
    int warp = (blockIdx.x * blockDim.x + threadIdx.x) >> 5;
    int lane = threadIdx.x & 31;
    const int total = NSR + NQ * FF;
    if (warp >= total) return;

    const float* src;
    __nv_bfloat162* dst;
    if (warp < NSR) {
        int s = warp / FF, f = warp % FF;
        src = (f < FG) ? sg + (s * FG + f) * D : sl + (s * FL + (f - FG)) * D;
        dst = reinterpret_cast<__nv_bfloat162*>(g_Sb + (size_t)warp * D);
    } else {
        int v = warp - NSR;
        int q = v / FF, f = v % FF;
        src = (f < FG) ? qg + (q * FG + f) * D : ql + (q * FL + (f - FG)) * D;
        dst = reinterpret_cast<__nv_bfloat162*>(g_Qb + (size_t)v * D);
    }

    float4 v[4];
    float ss = 0.f;
#pragma unroll
    for (int i = 0; i < 4; i++) {
        v[i] = reinterpret_cast<const float4*>(src)[lane + 32 * i];
        ss += v[i].x * v[i].x + v[i].y * v[i].y + v[i].z * v[i].z + v[i].w * v[i].w;
    }
#pragma unroll
    for (int o = 16; o; o >>= 1) ss += __shfl_xor_sync(0xFFFFFFFFu, ss, o);
    float inv = 1.0f / fmaxf(sqrtf(ss), 1e-12f);

#pragma unroll
    for (int i = 0; i < 4; i++) {
        __nv_bfloat162 h0 = __float22bfloat162_rn(make_float2(v[i].x * inv, v[i].y * inv));
        __nv_bfloat162 h1 = __float22bfloat162_rn(make_float2(v[i].z * inv, v[i].w * inv));
        dst[2 * (lane + 32 * i) + 0] = h0;
        dst[2 * (lane + 32 * i) + 1] = h1;
    }
}

// ---------------------------------------------------------------------------
// Kernel 1b: zero the fro2 accumulator
// ---------------------------------------------------------------------------
__global__ void zero_kernel()
{
    int t = blockIdx.x * blockDim.x + threadIdx.x;
    if (t < NS * NQ) g_fro2[t] = 0.f;
}

// ---------------------------------------------------------------------------
// Kernel 2: tensor-core fused distance kernel.
// CTA = (M tile tm of flat support rows, query q): C[128x80] = A_tile * B_q^T,
// epilogue: per-row sum of (1-c)^2, scattered to fro2[row/80][q] by atomicAdd.
// 8 warps in 4x2 grid; per warp 2 m16-tiles x 5 n8-tiles; K chunked by 64.
// ---------------------------------------------------------------------------
__global__ __launch_bounds__(256) void dist_kernel()
{
    __shared__ __align__(16) __nv_bfloat16 As[MT][LDA];
    __shared__ __align__(16) __nv_bfloat16 Bs[FF][LDA];
    __shared__ float red[MT];

    const int q  = blockIdx.x;
    const int tm = blockIdx.y;
    const int tid  = threadIdx.x;
    const int lane = tid & 31;
    const int wid  = tid >> 5;
    const int wy   = wid >> 1;          // 0..3 -> 32 M rows each
    const int wx   = wid & 1;           // 0..1 -> 40 N cols each
    const int qr   = lane >> 2;         // 0..7
    const int qc   = lane & 3;          // 0..3

    const __nv_bfloat16* __restrict__ Bg = g_Qb + (size_t)q * FF * D;

    float acc[2][5][4];
#pragma unroll
    for (int mt = 0; mt < 2; mt++)
#pragma unroll
        for (int nt = 0; nt < 5; nt++)
#pragma unroll
            for (int r = 0; r < 4; r++) acc[mt][nt][r] = 0.f;

    for (int k0 = 0; k0 < D; k0 += KC) {
        // --- load A chunk: 128 rows x 64 k (uint4 = 8 bf16), 4 per thread ---
#pragma unroll
        for (int i = 0; i < 4; i++) {
            int idx = tid + i * 256;          // 0..1023
            int row = idx >> 3, colv = idx & 7;
            int grow = tm * MT + row;
            if (grow > NSR - 1) grow = NSR - 1;   // clamp (masked in epilogue)
            uint4 v = *reinterpret_cast<const uint4*>(g_Sb + (size_t)grow * D + k0 + colv * 8);
            *reinterpret_cast<uint4*>(&As[row][colv * 8]) = v;
        }
        // --- load B chunk: 80 rows x 64 k -> 640 uint4 ---
#pragma unroll
        for (int i = 0; i < 3; i++) {
            int idx = tid + i * 256;
            if (idx < FF * 8) {
                int row = idx >> 3, colv = idx & 7;
                uint4 v = *reinterpret_cast<const uint4*>(Bg + (size_t)row * D + k0 + colv * 8);
                *reinterpret_cast<uint4*>(&Bs[row][colv * 8]) = v;
            }
        }
        __syncthreads();

#pragma unroll
        for (int ks = 0; ks < KC / 16; ks++) {
            const int k = ks * 16;
            uint32_t a[2][4];
#pragma unroll
            for (int mt = 0; mt < 2; mt++) {
                int r = wy * 32 + mt * 16 + qr;
                a[mt][0] = *reinterpret_cast<const uint32_t*>(&As[r][k + qc * 2]);
                a[mt][1] = *reinterpret_cast<const uint32_t*>(&As[r + 8][k + qc * 2]);
                a[mt][2] = *reinterpret_cast<const uint32_t*>(&As[r][k + qc * 2 + 8]);
                a[mt][3] = *reinterpret_cast<const uint32_t*>(&As[r + 8][k + qc * 2 + 8]);
            }
#pragma unroll
            for (int nt = 0; nt < 5; nt++) {
                int rn = wx * 40 + nt * 8 + qr;
                uint32_t b0 = *reinterpret_cast<const uint32_t*>(&Bs[rn][k + qc * 2]);
                uint32_t b1 = *reinterpret_cast<const uint32_t*>(&Bs[rn][k + qc * 2 + 8]);
                mma16816(acc[0][nt], a[0], b0, b1);
                mma16816(acc[1][nt], a[1], b0, b1);
            }
        }
        __syncthreads();
    }

    // --- epilogue: per-thread row partials of sum (1 - c)^2 ---
    if (tid < MT) red[tid] = 0.f;
    __syncthreads();

#pragma unroll
    for (int mt = 0; mt < 2; mt++) {
        float p0 = 0.f, p1 = 0.f;
#pragma unroll
        for (int nt = 0; nt < 5; nt++) {
            float d0 = 1.0f - acc[mt][nt][0];
            float d1 = 1.0f - acc[mt][nt][1];
            float d2 = 1.0f - acc[mt][nt][2];
            float d3 = 1.0f - acc[mt][nt][3];
            p0 += d0 * d0 + d1 * d1;   // row qr
            p1 += d2 * d2 + d3 * d3;   // row qr + 8
        }
        int r = wy * 32 + mt * 16 + qr;
        atomicAdd(&red[r], p0);
        atomicAdd(&red[r + 8], p1);
    }
    __syncthreads();

    if (tid < MT) {
        int grow = tm * MT + tid;
        if (grow < NSR)
            atomicAdd(&g_fro2[(grow / FF) * NQ + q], red[tid]);
    }
}

// ---------------------------------------------------------------------------
// Kernel 3: class-mean + negate -> logits [nQ, WAY]
// ---------------------------------------------------------------------------
__global__ void logits_kernel(const long long* __restrict__ labels,
                              float* __restrict__ out)
{
    int t = blockIdx.x * blockDim.x + threadIdx.x;
    if (t >= NQ * WAY) return;
    int q = t / WAY, c = t % WAY;
    float sum = 0.f; int cnt = 0;
#pragma unroll
    for (int s = 0; s < NS; s++) {
        if ((int)labels[s] == c) { sum += g_fro2[s * NQ + q]; cnt++; }
    }
    out[t] = -(2.0f * sum) / (float)cnt;
}

// ---------------------------------------------------------------------------
extern "C" void kernel_launch(void* const* d_in, const int* in_sizes, int n_in,
                              void* d_out, int out_size)
{
    const float*     sg     = (const float*)d_in[0];   // [25,16,512]
    const float*     sl     = (const float*)d_in[1];   // [25,64,512]
    const long long* labels = (const long long*)d_in[2];
    const float*     qg     = (const float*)d_in[3];   // [200,16,512]
    const float*     ql     = (const float*)d_in[4];   // [200,64,512]
    float*           out    = (float*)d_out;           // [200,5]

    int nvec = NSR + NQ * FF;  // 18000 vectors, one warp each
    norm_kernel<<<(nvec * 32 + 255) / 256, 256>>>(sg, sl, qg, ql);

    zero_kernel<<<(NS * NQ + 255) / 256, 256>>>();

    dist_kernel<<<dim3(NQ, NMT), 256>>>();

    logits_kernel<<<(NQ * WAY + 255) / 256, 256>>>(labels, out);
}